// round 7
// baseline (speedup 1.0000x reference)
#include <cuda_runtime.h>
#include <math.h>
#include <complex>

#define TT 50
#define NB 50
#define NC 4096
#define NCH (NB*NC)          // 204800 channels
#define NCH2 (NCH/2)         // 102400 packed channel-pairs
#define PADLEN 49
#define RS 99                // smem row stride in u64 (exact live set; stride 99 -> conflict-free)
#define THREADS 256

typedef unsigned long long u64;

struct Coefs { float c[2][2][5]; }; // [band][section][b0, a1, a2, zi0, zi1]

// per-channel-pair packed (1/s_lo, 1/s_hi); 2 bands x 102400 pairs = 1.6 MB
__device__ __align__(16) u64 g_is[2][NCH2];

// ---------------- packed f32x2 helpers (sm_103a) ----------------
__device__ __forceinline__ u64 pk2(float lo, float hi) {
    u64 d; asm("mov.b64 %0, {%1, %2};" : "=l"(d) : "f"(lo), "f"(hi)); return d;
}
__device__ __forceinline__ void upk2(u64 v, float& lo, float& hi) {
    asm("mov.b64 {%0, %1}, %2;" : "=f"(lo), "=f"(hi) : "l"(v));
}
__device__ __forceinline__ u64 fma2(u64 a, u64 b, u64 c) {
    u64 d; asm("fma.rn.f32x2 %0, %1, %2, %3;" : "=l"(d) : "l"(a), "l"(b), "l"(c)); return d;
}
__device__ __forceinline__ u64 add2(u64 a, u64 b) {
    u64 d; asm("add.rn.f32x2 %0, %1, %2;" : "=l"(d) : "l"(a), "l"(b)); return d;
}
__device__ __forceinline__ u64 mul2(u64 a, u64 b) {
    u64 d; asm("mul.rn.f32x2 %0, %1, %2;" : "=l"(d) : "l"(a), "l"(b)); return d;
}
__device__ __forceinline__ u64 neg2(u64 a) { return a ^ 0x8000000080000000ull; }

// DF2T biquad step with b1 = 0, b2 = -b0 (always true for these bandpass sections):
//   y  = b0*x + z0 ; z0 = z1 - a1*y ; z1 = -b0*x - a2*y
__device__ __forceinline__ u64 secstep(u64 X, u64 b0p, u64 na1p, u64 na2p, u64& z0, u64& z1) {
    u64 u = mul2(b0p, X);
    u64 y = add2(u, z0);
    z0 = fma2(na1p, y, z1);
    z1 = fma2(na2p, y, neg2(u));
    return y;
}

#define STEP2(X) do { u64 _y0 = secstep((X), b0p0, na1p0, na2p0, z00, z01); \
                      (void)secstep(_y0, b0p1, na1p1, na2p1, z10, z11); } while (0)
#define STEP2W(X, W) do { u64 _y0 = secstep((X), b0p0, na1p0, na2p0, z00, z01); \
                          (W) = secstep(_y0, b0p1, na1p1, na2p1, z10, z11); } while (0)

// Buffer layout (per-thread, 99 u64 slots):
//   x[j]            -> B[49+j]            (j = 0..49)
//   fwd w_k         -> B[k-49]  k=49..97  (slots 0..48, previously empty)
//                      B[98]    k=98      (over dead x[49])
//                      B[196-k] k=99..147 (over just-consumed x[147-k])
//   final y[t]      -> B[t] t=0..48, y[49] -> B[98] (slot freed by backward read)
__global__ void __launch_bounds__(THREADS, 1)
filtfilt_kernel(const u64* __restrict__ xin, u64* __restrict__ yout, Coefs cf)
{
    extern __shared__ u64 sm[];
    const int tid = threadIdx.x;
    u64* B = sm + tid * RS;                       // per-thread private row, no barriers
    const int band = blockIdx.y;
    const unsigned gch = blockIdx.x * (unsigned)THREADS + tid;   // packed channel-pair index

    const float b00 = cf.c[band][0][0], a01 = cf.c[band][0][1], a02 = cf.c[band][0][2];
    const float z00c = cf.c[band][0][3], z01c = cf.c[band][0][4];
    const float b10 = cf.c[band][1][0], a11 = cf.c[band][1][1], a12 = cf.c[band][1][2];
    const float z10c = cf.c[band][1][3], z11c = cf.c[band][1][4];

    const u64 b0p0 = pk2(b00, b00), na1p0 = pk2(-a01, -a01), na2p0 = pk2(-a02, -a02);
    const u64 b0p1 = pk2(b10, b10), na1p1 = pk2(-a11, -a11), na2p1 = pk2(-a12, -a12);
    const u64 zi00p = pk2(z00c, z00c), zi01p = pk2(z01c, z01c);
    const u64 zi10p = pk2(z10c, z10c), zi11p = pk2(z11c, z11c);

    // ---- load input (coalesced 64-bit): x[t] -> B[49+t] ----
#pragma unroll 5
    for (int t = 0; t < TT; t++)
        B[PADLEN + t] = xin[(unsigned)t * NCH2 + gch];

    const u64 x0 = B[PADLEN], xT = B[PADLEN + TT - 1];
    const u64 tw0 = add2(x0, x0), twT = add2(xT, xT);

    // ---- forward pass; extensions computed on the fly ----
    const u64 e0 = add2(tw0, neg2(B[98]));        // ext[0] = 2x0 - x[49]
    u64 z00 = mul2(zi00p, e0), z01 = mul2(zi01p, e0);
    u64 z10 = mul2(zi10p, e0), z11 = mul2(zi11p, e0);

    u64 xv = B[98];                               // x[49] (input of warmup step 0)
    // warmup k=0..48: ext[k] = 2x0 - x[49-k]; outputs discarded
#pragma unroll 7
    for (int k = 0; k < 49; k++) {
        u64 cur = xv;
        xv = B[97 - k];                           // next: x[48-k]; at k=48 -> B[49]=x[0]
        STEP2(add2(tw0, neg2(cur)));
    }
    // main k=49..97: input x[k-49] (prefetched), write w_k -> B[k-49]
#pragma unroll 7
    for (int k = 49; k < 98; k++) {
        u64 cur = xv;
        xv = B[k + 1];                            // next x; at k=97 -> B[98]=x[49]
        u64 w; STEP2W(cur, w);
        B[k - 49] = w;
    }
    // k=98: input x[49] (prefetched), write w_98 -> B[98]
    {
        u64 cur = xv;
        xv = B[97];                               // x[48], input basis for k=99
        u64 w; STEP2W(cur, w);
        B[98] = w;
    }
    // tail k=99..147: ext[k] = 2x49 - x[147-k]; write w_k -> B[196-k]
#pragma unroll 7
    for (int k = 99; k < 148; k++) {
        u64 cur = xv;
        xv = B[195 - k];                          // next x[146-k]; harmless read at k=147
        u64 w; STEP2W(add2(twT, neg2(cur)), w);
        B[196 - k] = w;
    }

    // ---- backward pass over reversed forward output ----
    u64 rv = B[49];                               // w_147
    const u64 yr0 = rv;
    z00 = mul2(zi00p, yr0); z01 = mul2(zi01p, yr0);
    z10 = mul2(zi10p, yr0); z11 = mul2(zi11p, yr0);

    // warmup m=0..48: consume w_{147-m} at B[49+m]; outputs discarded
#pragma unroll 7
    for (int m = 0; m < 49; m++) {
        u64 cur = rv;
        rv = B[50 + m];                           // next; at m=48 -> B[98]=w_98
        STEP2(cur);
    }
    u64 sum = 0ull;
    // m=49: consume w_98 at B[98]; produce y[49] -> B[98]
    {
        u64 cur = rv;
        rv = B[48];                               // w_97 (next)
        u64 y1; STEP2W(cur, y1);
        B[98] = y1;
        sum = add2(sum, y1);
    }
    // m=50..98: consume w_{147-m} at B[98-m]; produce y[98-m] -> same slot
#pragma unroll 7
    for (int m = 50; m < 99; m++) {
        u64 cur = rv;
        rv = B[97 - m];                           // next; harmless read at m=98 (B[-1]? no: 97-98=-1)
        u64 y1; STEP2W(cur, y1);
        B[98 - m] = y1;
        sum = add2(sum, y1);
    }

    // ---- demean (channel's own mean), two-pass variance (ddof=1) ----
    float sl, sh;
    upk2(sum, sl, sh);
    const u64 mp = pk2(sl * 0.02f, sh * 0.02f);

    u64* obase = yout + (unsigned)band * (TT * NCH2) + gch;
    u64 sq = 0ull;
#pragma unroll 7
    for (int t = 0; t < 49; t++) {
        u64 d = add2(B[t], neg2(mp));
        sq = fma2(d, d, sq);
        obase[(unsigned)t * NCH2] = d;
    }
    {
        u64 d = add2(B[98], neg2(mp));            // y[49]
        sq = fma2(d, d, sq);
        obase[49u * NCH2] = d;
    }
    float ql, qh;
    upk2(sq, ql, qh);
    g_is[band][gch] = pk2(rsqrtf(ql * (1.0f / 49.0f)), rsqrtf(qh * (1.0f / 49.0f)));
}

// Reference's _tensor_zscore broadcasts m[:,None,:]/s[:,None,:] ([B,1,C]) against [T,B,C]
// with T==B: out[t,b,c] = ydm[t,b,c] * (1/s)[channel (b=t, c)] (residual mean ~0).
__global__ void __launch_bounds__(256)
scale_kernel(u64* __restrict__ out)
{
    const unsigned p = blockIdx.x * 256u + threadIdx.x;
    const unsigned i2 = p * 2u;                            // even u64 index
    const unsigned band = i2 / (unsigned)(TT * NCH2);
    const unsigned rem  = i2 - band * (unsigned)(TT * NCH2);
    const unsigned t    = rem / (unsigned)NCH2;
    const unsigned q    = rem - t * (unsigned)NCH2;
    const unsigned cp   = q & 2047u;

    ulonglong2 v = *reinterpret_cast<ulonglong2*>(out + i2);
    const ulonglong2 s = *reinterpret_cast<const ulonglong2*>(&g_is[band][t * 2048u + cp]);
    v.x = mul2(v.x, s.x);
    v.y = mul2(v.y, s.y);
    *reinterpret_cast<ulonglong2*>(out + i2) = v;
}

// ---------------- host: scipy-equivalent butter bandpass + sosfilt_zi ----------------
static void design_band(double w1, double w2, float sec[2][5])
{
    const int n = 2;
    const double fs = 2.0, fs2 = 4.0;
    const double PI = 3.14159265358979323846;
    double warped0 = 2.0 * fs * tan(PI * w1 / fs);
    double warped1 = 2.0 * fs * tan(PI * w2 / fs);
    double bw = warped1 - warped0;
    double wo = sqrt(warped0 * warped1);

    std::complex<double> plp[2], disc[2], p_bp[4];
    for (int k = 1; k <= n; k++) {
        std::complex<double> p = -std::exp(std::complex<double>(0.0, PI * (2 * k - 1) / (2.0 * n)));
        plp[k - 1] = p * (bw / 2.0);
        disc[k - 1] = std::sqrt(plp[k - 1] * plp[k - 1] - std::complex<double>(wo * wo, 0.0));
    }
    p_bp[0] = plp[0] + disc[0]; p_bp[1] = plp[1] + disc[1];
    p_bp[2] = plp[0] - disc[0]; p_bp[3] = plp[1] - disc[1];

    std::complex<double> prod(1.0, 0.0);
    for (int i = 0; i < 4; i++) prod *= (std::complex<double>(fs2, 0.0) - p_bp[i]);
    double gain = pow(bw, n) * pow(fs2, n) / prod.real();

    std::complex<double> pos[2]; int np = 0;
    for (int i = 0; i < 4; i++) {
        std::complex<double> pd = (std::complex<double>(fs2, 0.0) + p_bp[i]) /
                                  (std::complex<double>(fs2, 0.0) - p_bp[i]);
        if (pd.imag() > 0.0 && np < 2) pos[np++] = pd;
    }

    double sb[2][3], sa[2][3];
    for (int i = 0; i < 2; i++) {
        double g = (i == 0) ? gain : 1.0;
        sb[i][0] = g; sb[i][1] = 0.0; sb[i][2] = -g;
        sa[i][0] = 1.0; sa[i][1] = -2.0 * pos[i].real(); sa[i][2] = std::norm(pos[i]);
    }
    double scale = 1.0;
    for (int s = 0; s < 2; s++) {
        double b0 = sb[s][0], b1 = sb[s][1], b2 = sb[s][2];
        double a1 = sa[s][1], a2 = sa[s][2];
        double B0 = b1 - a1 * b0, B1 = b2 - a2 * b0, det = 1.0 + a1 + a2;
        double zz0 = scale * (B0 + B1) / det;
        double zz1 = scale * ((1.0 + a1) * B1 - a2 * B0) / det;
        scale *= (b0 + b1 + b2) / (1.0 + a1 + a2);
        sec[s][0] = (float)b0; sec[s][1] = (float)a1; sec[s][2] = (float)a2;
        sec[s][3] = (float)zz0; sec[s][4] = (float)zz1;
    }
}

extern "C" void kernel_launch(void* const* d_in, const int* in_sizes, int n_in,
                              void* d_out, int out_size)
{
    (void)in_sizes; (void)n_in; (void)out_size;
    Coefs cf;
    design_band(0.05, 0.15, cf.c[0]);
    design_band(0.20, 0.40, cf.c[1]);

    const int smem = THREADS * RS * 8;   // 202,752 B -> 1 CTA/SM, 8 warps
    cudaFuncSetAttribute(filtfilt_kernel, cudaFuncAttributeMaxDynamicSharedMemorySize, smem);

    dim3 grid(NCH2 / THREADS, 2);        // (400, 2)
    filtfilt_kernel<<<grid, THREADS, smem>>>((const u64*)d_in[0], (u64*)d_out, cf);

    scale_kernel<<<(2 * TT * NCH2 / 2) / 256, 256>>>((u64*)d_out);
}

// round 8
// speedup vs baseline: 1.3602x; 1.3602x over previous
#include <cuda_runtime.h>

typedef unsigned int u32;
#define HD __host__ __device__

// ============ constexpr double math (compile-time filter design) ============
struct CD { double re, im; };
HD constexpr CD cadd(CD a, CD b){ return {a.re+b.re, a.im+b.im}; }
HD constexpr CD csub(CD a, CD b){ return {a.re-b.re, a.im-b.im}; }
HD constexpr CD cmul(CD a, CD b){ return {a.re*b.re - a.im*b.im, a.re*b.im + a.im*b.re}; }
HD constexpr CD cdiv(CD a, CD b){ double d = b.re*b.re + b.im*b.im;
    return {(a.re*b.re + a.im*b.im)/d, (a.im*b.re - a.re*b.im)/d}; }
HD constexpr double d_sqrt(double x){ double y = x > 1.0 ? x : 1.0;
    for (int i = 0; i < 80; i++) y = 0.5*(y + x/y); return y; }
HD constexpr CD c_sqrt(CD z){ double r = d_sqrt(z.re*z.re + z.im*z.im);
    double u = d_sqrt((r + z.re)*0.5); double v = d_sqrt((r - z.re)*0.5);
    if (z.im < 0.0) v = -v; return {u, v}; }
HD constexpr double d_sin(double x){ double t = x, s = x, x2 = x*x;
    for (int k = 1; k <= 14; k++){ t *= -x2/((2.0*k)*(2.0*k+1.0)); s += t; } return s; }
HD constexpr double d_cos(double x){ double t = 1.0, s = 1.0, x2 = x*x;
    for (int k = 1; k <= 14; k++){ t *= -x2/((2.0*k-1.0)*(2.0*k)); s += t; } return s; }
HD constexpr double d_tan(double x){ return d_sin(x)/d_cos(x); }

// scipy-equivalent butter(2) bandpass + sosfilt_zi, fs=2 (b1=0, b2=-b0 per section)
struct Sos { double b0[2], a1[2], a2[2], zi0[2], zi1[2]; };
HD constexpr Sos design(double w1, double w2){
    const double PI = 3.141592653589793238462643383279502884;
    double warped0 = 4.0 * d_tan(PI * w1 * 0.5);
    double warped1 = 4.0 * d_tan(PI * w2 * 0.5);
    double bw = warped1 - warped0;
    double wo = d_sqrt(warped0 * warped1);
    double s = d_sqrt(0.5);
    CD plp[2] = { {-s*bw*0.5, -s*bw*0.5}, { s*bw*0.5, -s*bw*0.5} };  // -exp(i pi(2k-1)/4) * bw/2
    CD disc[2] = { c_sqrt(csub(cmul(plp[0],plp[0]), CD{wo*wo, 0.0})),
                   c_sqrt(csub(cmul(plp[1],plp[1]), CD{wo*wo, 0.0})) };
    CD pbp[4] = { cadd(plp[0],disc[0]), cadd(plp[1],disc[1]),
                  csub(plp[0],disc[0]), csub(plp[1],disc[1]) };
    CD prod = {1.0, 0.0};
    for (int i = 0; i < 4; i++) prod = cmul(prod, csub(CD{4.0,0.0}, pbp[i]));
    double gain = bw*bw*16.0 / prod.re;
    CD pos[2] = {}; int np = 0;
    for (int i = 0; i < 4; i++){
        CD pd = cdiv(cadd(CD{4.0,0.0}, pbp[i]), csub(CD{4.0,0.0}, pbp[i]));
        if (pd.im > 0.0 && np < 2){ pos[np] = pd; np++; }
    }
    Sos S{};
    S.b0[0] = gain; S.b0[1] = 1.0;
    for (int i = 0; i < 2; i++){
        S.a1[i] = -2.0*pos[i].re;
        S.a2[i] = pos[i].re*pos[i].re + pos[i].im*pos[i].im;
    }
    double scale = 1.0;
    for (int sI = 0; sI < 2; sI++){
        double b0 = S.b0[sI], b2 = -S.b0[sI], a1 = S.a1[sI], a2 = S.a2[sI];
        double B0 = -a1*b0, B1 = b2 - a2*b0, det = 1.0 + a1 + a2;
        S.zi0[sI] = scale * (B0 + B1) / det;
        S.zi1[sI] = scale * ((1.0 + a1)*B1 - a2*B0) / det;
        scale *= (b0 + b2) / (1.0 + a1 + a2);
    }
    return S;
}

// L[t][i]: full filtfilt (odd-ext 49, fwd, rev, bwd, rev, slice, demean over t)
// applied to basis vector e_i, double precision, then cast to float.
struct LM { float m[50][50]; };
HD constexpr LM build_lm(int band){
    Sos S = band ? design(0.20, 0.40) : design(0.05, 0.15);
    LM r{};
    for (int i = 0; i < 50; i++){
        double e[148] = {};
        for (int k = 0; k < 49; k++)  e[k]      = 2.0*(i==0)  - (double)((49-k)==i);
        for (int j = 0; j < 50; j++)  e[49+j]   = (double)(j==i);
        for (int j = 0; j < 49; j++)  e[99+j]   = 2.0*(i==49) - (double)((48-j)==i);
        for (int pass = 0; pass < 2; pass++){
            double e0 = e[0];
            double z00 = S.zi0[0]*e0, z01 = S.zi1[0]*e0;
            double z10 = S.zi0[1]*e0, z11 = S.zi1[1]*e0;
            for (int k = 0; k < 148; k++){
                double v  = e[k];
                double y0 = S.b0[0]*v  + z00; z00 = z01 - S.a1[0]*y0; z01 = -S.b0[0]*v  - S.a2[0]*y0;
                double y1 = S.b0[1]*y0 + z10; z10 = z11 - S.a1[1]*y1; z11 = -S.b0[1]*y0 - S.a2[1]*y1;
                e[k] = y1;
            }
            for (int k = 0; k < 74; k++){ double t = e[k]; e[k] = e[147-k]; e[147-k] = t; }
        }
        double mean = 0.0;
        for (int t = 0; t < 50; t++) mean += e[49+t];
        mean *= 0.02;
        for (int t = 0; t < 50; t++) r.m[t][i] = (float)(e[49+t] - mean);
    }
    return r;
}

// ============ fused kernel: y = L x (FFMA-imm GEMM) + zscore ============
#define OUT_B 10240000u   // band stride (50*50*4096)
#define OUT_T 204800u     // t stride   (50*4096)

template<int B>
__device__ __forceinline__ void proc(const float xr[50], float* ob, int b, int lane,
                                     float (&is_sm)[2][50][32])
{
    constexpr LM lf = build_lm(B);   // compile-time; coefficients fold to FFMA immediates
    float sq = 0.f;
#pragma unroll
    for (int t = 0; t < 50; t++){
        float a0 = 0.f, a1 = 0.f, a2 = 0.f, a3 = 0.f;
#pragma unroll
        for (int s = 0; s < 48; s += 4){
            a0 = fmaf(xr[s+0], lf.m[t][s+0], a0);
            a1 = fmaf(xr[s+1], lf.m[t][s+1], a1);
            a2 = fmaf(xr[s+2], lf.m[t][s+2], a2);
            a3 = fmaf(xr[s+3], lf.m[t][s+3], a3);
        }
        a0 = fmaf(xr[48], lf.m[t][48], a0);
        a1 = fmaf(xr[49], lf.m[t][49], a1);
        float y = (a0 + a1) + (a2 + a3);
        sq = fmaf(y, y, sq);
        ob[(u32)B * OUT_B + (u32)t * OUT_T] = y;
    }
    is_sm[B][b][lane] = rsqrtf(sq * (1.0f / 49.0f));
}

__global__ void __launch_bounds__(512, 1)
fused_kernel(const float* __restrict__ xg, float* __restrict__ out)
{
    __shared__ float is_sm[2][50][32];
    const int lane = threadIdx.x & 31;
    const int w    = threadIdx.x >> 5;                 // 0..15
    const u32 c    = blockIdx.x * 32u + (u32)lane;
    const int nrows = (w < 2) ? 4 : 3;                 // rows {w, w+16, w+32 (,w+48)}

#pragma unroll 1
    for (int j = 0; j < nrows; j++){
        const int b = w + 16 * j;
        const float* xb = xg + (u32)b * 4096u + c;
        float xr[50];
#pragma unroll
        for (int s = 0; s < 50; s++) xr[s] = __ldg(xb + (u32)s * OUT_T);
        float* ob = out + (u32)b * 4096u + c;
        proc<0>(xr, ob, b, lane, is_sm);
        proc<1>(xr, ob, b, lane, is_sm);
    }
    __syncthreads();

    // out[t,b,c] *= 1/s of channel (b'=t, c)   (reference's [B,1,C] broadcast vs [T,B,C])
#pragma unroll 1
    for (int j = 0; j < nrows; j++){
        const int b = w + 16 * j;
        float* ob = out + (u32)b * 4096u + c;
#pragma unroll 1
        for (int band = 0; band < 2; band++){
#pragma unroll
            for (int t = 0; t < 50; t++){
                const u32 idx = (u32)band * OUT_B + (u32)t * OUT_T;
                ob[idx] *= is_sm[band][t][lane];
            }
        }
    }
}

extern "C" void kernel_launch(void* const* d_in, const int* in_sizes, int n_in,
                              void* d_out, int out_size)
{
    (void)in_sizes; (void)n_in; (void)out_size;
    fused_kernel<<<128, 512>>>((const float*)d_in[0], (float*)d_out);
}

// round 9
// speedup vs baseline: 1.6891x; 1.2418x over previous
#include <cuda_runtime.h>

typedef unsigned int u32;
#define HD __host__ __device__

#define OUT_B 10240000u   // band stride (50*50*4096)
#define OUT_T 204800u     // t stride   (50*4096)

// per-channel 1/s: [band][b*4096+c]
__device__ __align__(16) float g_is[2][204800];

// ============ constexpr double math (compile-time filter design) ============
struct CD { double re, im; };
HD constexpr CD cadd(CD a, CD b){ return {a.re+b.re, a.im+b.im}; }
HD constexpr CD csub(CD a, CD b){ return {a.re-b.re, a.im-b.im}; }
HD constexpr CD cmul(CD a, CD b){ return {a.re*b.re - a.im*b.im, a.re*b.im + a.im*b.re}; }
HD constexpr CD cdiv(CD a, CD b){ double d = b.re*b.re + b.im*b.im;
    return {(a.re*b.re + a.im*b.im)/d, (a.im*b.re - a.re*b.im)/d}; }
HD constexpr double d_sqrt(double x){ double y = x > 1.0 ? x : 1.0;
    for (int i = 0; i < 80; i++) y = 0.5*(y + x/y); return y; }
HD constexpr CD c_sqrt(CD z){ double r = d_sqrt(z.re*z.re + z.im*z.im);
    double u = d_sqrt((r + z.re)*0.5); double v = d_sqrt((r - z.re)*0.5);
    if (z.im < 0.0) v = -v; return {u, v}; }
HD constexpr double d_sin(double x){ double t = x, s = x, x2 = x*x;
    for (int k = 1; k <= 14; k++){ t *= -x2/((2.0*k)*(2.0*k+1.0)); s += t; } return s; }
HD constexpr double d_cos(double x){ double t = 1.0, s = 1.0, x2 = x*x;
    for (int k = 1; k <= 14; k++){ t *= -x2/((2.0*k-1.0)*(2.0*k)); s += t; } return s; }
HD constexpr double d_tan(double x){ return d_sin(x)/d_cos(x); }

// scipy-equivalent butter(2) bandpass + sosfilt_zi, fs=2 (b1=0, b2=-b0 per section)
struct Sos { double b0[2], a1[2], a2[2], zi0[2], zi1[2]; };
HD constexpr Sos design(double w1, double w2){
    const double PI = 3.141592653589793238462643383279502884;
    double warped0 = 4.0 * d_tan(PI * w1 * 0.5);
    double warped1 = 4.0 * d_tan(PI * w2 * 0.5);
    double bw = warped1 - warped0;
    double wo = d_sqrt(warped0 * warped1);
    double s = d_sqrt(0.5);
    CD plp[2] = { {-s*bw*0.5, -s*bw*0.5}, { s*bw*0.5, -s*bw*0.5} };
    CD disc[2] = { c_sqrt(csub(cmul(plp[0],plp[0]), CD{wo*wo, 0.0})),
                   c_sqrt(csub(cmul(plp[1],plp[1]), CD{wo*wo, 0.0})) };
    CD pbp[4] = { cadd(plp[0],disc[0]), cadd(plp[1],disc[1]),
                  csub(plp[0],disc[0]), csub(plp[1],disc[1]) };
    CD prod = {1.0, 0.0};
    for (int i = 0; i < 4; i++) prod = cmul(prod, csub(CD{4.0,0.0}, pbp[i]));
    double gain = bw*bw*16.0 / prod.re;
    CD pos[2] = {}; int np = 0;
    for (int i = 0; i < 4; i++){
        CD pd = cdiv(cadd(CD{4.0,0.0}, pbp[i]), csub(CD{4.0,0.0}, pbp[i]));
        if (pd.im > 0.0 && np < 2){ pos[np] = pd; np++; }
    }
    Sos S{};
    S.b0[0] = gain; S.b0[1] = 1.0;
    for (int i = 0; i < 2; i++){
        S.a1[i] = -2.0*pos[i].re;
        S.a2[i] = pos[i].re*pos[i].re + pos[i].im*pos[i].im;
    }
    double scale = 1.0;
    for (int sI = 0; sI < 2; sI++){
        double b0 = S.b0[sI], b2 = -S.b0[sI], a1 = S.a1[sI], a2 = S.a2[sI];
        double B0 = -a1*b0, B1 = b2 - a2*b0, det = 1.0 + a1 + a2;
        S.zi0[sI] = scale * (B0 + B1) / det;
        S.zi1[sI] = scale * ((1.0 + a1)*B1 - a2*B0) / det;
        scale *= (b0 + b2) / (1.0 + a1 + a2);
    }
    return S;
}

// L[t][i]: full filtfilt (odd-ext 49, fwd, rev, bwd, rev, slice, demean over t)
// applied to basis vector e_i, double precision, then cast to float.
struct LM { float m[50][50]; };
HD constexpr LM build_lm(int band){
    Sos S = band ? design(0.20, 0.40) : design(0.05, 0.15);
    LM r{};
    for (int i = 0; i < 50; i++){
        double e[148] = {};
        for (int k = 0; k < 49; k++)  e[k]      = 2.0*(i==0)  - (double)((49-k)==i);
        for (int j = 0; j < 50; j++)  e[49+j]   = (double)(j==i);
        for (int j = 0; j < 49; j++)  e[99+j]   = 2.0*(i==49) - (double)((48-j)==i);
        for (int pass = 0; pass < 2; pass++){
            double e0 = e[0];
            double z00 = S.zi0[0]*e0, z01 = S.zi1[0]*e0;
            double z10 = S.zi0[1]*e0, z11 = S.zi1[1]*e0;
            for (int k = 0; k < 148; k++){
                double v  = e[k];
                double y0 = S.b0[0]*v  + z00; z00 = z01 - S.a1[0]*y0; z01 = -S.b0[0]*v  - S.a2[0]*y0;
                double y1 = S.b0[1]*y0 + z10; z10 = z11 - S.a1[1]*y1; z11 = -S.b0[1]*y0 - S.a2[1]*y1;
                e[k] = y1;
            }
            for (int k = 0; k < 74; k++){ double t = e[k]; e[k] = e[147-k]; e[147-k] = t; }
        }
        double mean = 0.0;
        for (int t = 0; t < 50; t++) mean += e[49+t];
        mean *= 0.02;
        for (int t = 0; t < 50; t++) r.m[t][i] = (float)(e[49+t] - mean);
    }
    return r;
}

// ============ kernel 1: y = L x (FFMA-imm GEMM) + 1/s ============
template<int B>
__device__ __forceinline__ void proc(const float xr[50], float* ob, u32 ch)
{
    constexpr LM lf = build_lm(B);   // compile-time; coefficients fold to FFMA immediates
    float sq = 0.f;
#pragma unroll
    for (int t = 0; t < 50; t++){
        float a0 = 0.f, a1 = 0.f, a2 = 0.f, a3 = 0.f;
#pragma unroll
        for (int s = 0; s < 48; s += 4){
            a0 = fmaf(xr[s+0], lf.m[t][s+0], a0);
            a1 = fmaf(xr[s+1], lf.m[t][s+1], a1);
            a2 = fmaf(xr[s+2], lf.m[t][s+2], a2);
            a3 = fmaf(xr[s+3], lf.m[t][s+3], a3);
        }
        a0 = fmaf(xr[48], lf.m[t][48], a0);
        a1 = fmaf(xr[49], lf.m[t][49], a1);
        float y = (a0 + a1) + (a2 + a3);
        sq = fmaf(y, y, sq);
        ob[(u32)B * OUT_B + (u32)t * OUT_T] = y;
    }
    g_is[B][ch] = rsqrtf(sq * (1.0f / 49.0f));
}

__global__ void __launch_bounds__(256, 2)
gemm_kernel(const float* __restrict__ xg, float* __restrict__ out)
{
    const int lane = threadIdx.x & 31;
    const int w    = threadIdx.x >> 5;
    const u32 gw   = blockIdx.x * 8u + (u32)w;   // 0..6399 : warp = one (b, c-tile)
    const u32 b    = gw >> 7;                    // 0..49
    const u32 ct   = gw & 127u;                  // 0..127
    const u32 c    = ct * 32u + (u32)lane;
    const u32 ch   = b * 4096u + c;

    const float* xb = xg + ch;
    float xr[50];
#pragma unroll
    for (int s = 0; s < 50; s++) xr[s] = __ldg(xb + (u32)s * OUT_T);

    float* ob = out + ch;
    proc<0>(xr, ob, ch);
    proc<1>(xr, ob, ch);
}

// ============ kernel 2: out[band,t,b,c] *= 1/s[band][channel (b'=t, c)] ============
// (reference's _tensor_zscore broadcasts m[:,None,:]/s[:,None,:] ([B,1,C]) against
//  [T,B,C] with T==B; residual mean of already-demeaned y is ~0 and is dropped)
__global__ void __launch_bounds__(256)
scale4_kernel(float4* __restrict__ out)
{
    const u32 p    = blockIdx.x * 256u + threadIdx.x;   // 5,120,000 float4 threads
    const u32 f    = p * 4u;                            // float index
    const u32 band = f / OUT_B;
    const u32 rem  = f - band * OUT_B;
    const u32 t    = rem / OUT_T;
    const u32 q    = rem - t * OUT_T;
    const u32 c    = q & 4095u;                         // multiple of 4

    float4 v = out[p];
    const float4 s = *reinterpret_cast<const float4*>(&g_is[band][t * 4096u + c]);
    v.x *= s.x; v.y *= s.y; v.z *= s.z; v.w *= s.w;
    out[p] = v;
}

extern "C" void kernel_launch(void* const* d_in, const int* in_sizes, int n_in,
                              void* d_out, int out_size)
{
    (void)in_sizes; (void)n_in; (void)out_size;
    gemm_kernel<<<800, 256>>>((const float*)d_in[0], (float*)d_out);
    scale4_kernel<<<20000, 256>>>((float4*)d_out);
}